// round 8
// baseline (speedup 1.0000x reference)
#include <cuda_runtime.h>
#include <cstdint>

// Problem constants (fixed by the reference)
#define NQ       64            // qubits
#define NS       4096          // samples per unique circuit
#define NU       256           // unique circuits
#define NB       1024          // batch size
#define PARTS    8             // blocks per circuit
#define NSB      (NS / PARTS)  // samples per block = 512
#define CHUNKS_B (NSB / 32)    // 16 chunks of 32 samples
#define THREADS  256
#define NWARPS   (THREADS / 32)
#define GRID     (NU * PARTS)  // 2048

// Per-(circuit,part) partial energy sums and completion counter.
__device__ float        g_part[GRID];
__device__ unsigned int g_count;   // zero-initialized; reset by last block

// One ballot-transpose step. Ballots act directly on the 0/1 int components.
// Lane owns qubits (lane) and (lane+32). Column bit order is a consistent
// permutation of sample order (irrelevant for XOR-popcount counting).
__device__ __forceinline__ void tstep(const uint4 v, const uint32_t b,
                                      const uint32_t p,
                                      uint32_t& colA, uint32_t& colB)
{
    const uint32_t W0 = __ballot_sync(0xffffffffu, v.x);
    const uint32_t W1 = __ballot_sync(0xffffffffu, v.y);
    const uint32_t W2 = __ballot_sync(0xffffffffu, v.z);
    const uint32_t W3 = __ballot_sync(0xffffffffu, v.w);
    const uint32_t Wl = (b & 1) ? W1 : W0;
    const uint32_t Wh = (b & 1) ? W3 : W2;
    const uint32_t Ws = (b & 2) ? Wh : Wl;
    const uint32_t t  = Ws >> p;
    colA = (colA << 2) | (t & 1u)        | ((t >> 15) & 2u);
    colB = (colB << 2) | ((t >> 8) & 1u) | ((t >> 23) & 2u);
}

// One block per (circuit, eighth). Software-pipelined:
//   [load+transpose G0] [prefetch G1a] SYNC [consume G0 || G1a in flight]
//   [transpose G1a, load+transpose G1b] SYNC [consume G1]
__global__ void __launch_bounds__(THREADS)
energy_kernel(const int* __restrict__ samples,
              const int* __restrict__ idx,
              const float* __restrict__ bias,
              const float* __restrict__ kern,
              float* __restrict__ out)
{
    __shared__ uint32_t col[CHUNKS_B][NQ];   // 4 KB
    __shared__ float red[NWARPS];
    __shared__ bool s_last;

    const int tid  = threadIdx.x;
    const int lane = tid & 31;
    const int w    = tid >> 5;
    const int bx   = blockIdx.x;
    const int c    = bx >> 3;        // circuit
    const int part = bx & 7;         // eighth

    const uint4* base =
        (const uint4*)(samples + (size_t)c * (size_t)(NS * NQ))
        + (size_t)part * NSB * (NQ / 4);

    const uint32_t b = lane & 3;
    const uint32_t p = lane >> 2;

    // Tile decode (done once): tid -> upper-triangle tile of 16x16 grid.
    const bool doTile = (tid < 136);
    int I = 0, J = 0;
    {
        int t = tid;
        while (t >= 16 - I) { t -= 16 - I; I++; }
        J = I + t;
        if (!doTile) { I = 0; J = 0; }
    }
    const int q0 = I << 2, r0 = J << 2;
    const int qb = tid - 192;            // bias qubit for tid>=192

    int cnt[4][4];
    #pragma unroll
    for (int i = 0; i < 4; i++)
        #pragma unroll
        for (int j = 0; j < 4; j++)
            cnt[i][j] = 0;
    int n1 = 0;

    const uint4* PA = base + (size_t)w * 512;         // chunk w
    const uint4* PB = base + (size_t)(8 + w) * 512;   // chunk 8+w

    // ---------------- Group 0: load + transpose chunk w --------------------
    {
        uint32_t colA = 0u, colB = 0u;
        uint4 v[8];
        #pragma unroll
        for (int j = 0; j < 8; j++) v[j] = __ldcs(&PA[j * 32 + lane]);
        #pragma unroll
        for (int j = 0; j < 8; j++) tstep(v[j], b, p, colA, colB);
        #pragma unroll
        for (int j = 0; j < 8; j++) v[j] = __ldcs(&PA[(8 + j) * 32 + lane]);
        #pragma unroll
        for (int j = 0; j < 8; j++) tstep(v[j], b, p, colA, colB);
        col[w][lane]      = colA;
        col[w][lane + 32] = colB;
    }

    // Prefetch first half of chunk 8+w; stays in flight across the barrier
    // and through the group-0 consume below.
    uint4 u[8];
    #pragma unroll
    for (int j = 0; j < 8; j++) u[j] = __ldcs(&PB[j * 32 + lane]);

    __syncthreads();

    // ---------------- Consume group 0 (chunks 0..7) ------------------------
    if (doTile) {
        #pragma unroll
        for (int ch = 0; ch < 8; ch++) {
            const uint4 a4 = *(const uint4*)&col[ch][q0];
            const uint4 b4 = *(const uint4*)&col[ch][r0];
            const uint32_t a[4]  = {a4.x, a4.y, a4.z, a4.w};
            const uint32_t bb[4] = {b4.x, b4.y, b4.z, b4.w};
            #pragma unroll
            for (int i = 0; i < 4; i++)
                #pragma unroll
                for (int j = 0; j < 4; j++)
                    cnt[i][j] += __popc(a[i] ^ bb[j]);
        }
    }
    if (tid >= 192) {
        #pragma unroll
        for (int ch = 0; ch < 8; ch++) n1 += __popc(col[ch][qb]);
    }

    // ---------------- Group 1: transpose prefetched + load rest ------------
    {
        uint32_t colA = 0u, colB = 0u;
        #pragma unroll
        for (int j = 0; j < 8; j++) tstep(u[j], b, p, colA, colB);
        #pragma unroll
        for (int j = 0; j < 8; j++) u[j] = __ldcs(&PB[(8 + j) * 32 + lane]);
        #pragma unroll
        for (int j = 0; j < 8; j++) tstep(u[j], b, p, colA, colB);
        col[8 + w][lane]      = colA;
        col[8 + w][lane + 32] = colB;
    }
    __syncthreads();

    // ---------------- Consume group 1 (chunks 8..15) -----------------------
    if (doTile) {
        #pragma unroll
        for (int ch = 8; ch < 16; ch++) {
            const uint4 a4 = *(const uint4*)&col[ch][q0];
            const uint4 b4 = *(const uint4*)&col[ch][r0];
            const uint32_t a[4]  = {a4.x, a4.y, a4.z, a4.w};
            const uint32_t bb[4] = {b4.x, b4.y, b4.z, b4.w};
            #pragma unroll
            for (int i = 0; i < 4; i++)
                #pragma unroll
                for (int j = 0; j < 4; j++)
                    cnt[i][j] += __popc(a[i] ^ bb[j]);
        }
    }
    if (tid >= 192) {
        #pragma unroll
        for (int ch = 8; ch < 16; ch++) n1 += __popc(col[ch][qb]);
    }

    // ---------------- Fold K + bias ----------------------------------------
    float acc = 0.f;
    if (doTile) {
        #pragma unroll
        for (int i = 0; i < 4; i++) {
            #pragma unroll
            for (int j = 0; j < 4; j++) {
                const int q = q0 + i, r = r0 + j;
                float kv = kern[q * NQ + r];
                if (I != J) kv += kern[r * NQ + q];   // symmetry fold
                acc += kv * (float)(NSB - 2 * cnt[i][j]);
            }
        }
    }
    if (tid >= 192) acc += bias[qb] * (float)(NSB - 2 * n1);

    // ---------------- Reduction + fused gather ----------------------------
    #pragma unroll
    for (int o = 16; o > 0; o >>= 1)
        acc += __shfl_down_sync(0xffffffffu, acc, o);
    if (lane == 0) red[w] = acc;
    __syncthreads();

    if (tid == 0) {
        float s = 0.f;
        #pragma unroll
        for (int i = 0; i < NWARPS; i++) s += red[i];
        g_part[bx] = s;
        __threadfence();
        const unsigned int done = atomicAdd(&g_count, 1u);
        s_last = (done == GRID - 1);
    }
    __syncthreads();

    if (s_last) {
        __threadfence();
        for (int i = tid; i < NB; i += THREADS) {
            const int u2 = idx[i];
            const float* gp = &g_part[u2 * PARTS];
            float s = 0.f;
            #pragma unroll
            for (int q = 0; q < PARTS; q++) s += gp[q];
            out[i] = s * (1.0f / (float)NS);
        }
        if (tid == 0) g_count = 0u;   // reset for next graph replay
    }
}

extern "C" void kernel_launch(void* const* d_in, const int* in_sizes, int n_in,
                              void* d_out, int out_size)
{
    const int*   samples = (const int*)d_in[0];
    const int*   idx     = (const int*)d_in[1];
    const float* bias    = (const float*)d_in[2];
    const float* kern    = (const float*)d_in[3];
    float*       out     = (float*)d_out;

    energy_kernel<<<GRID, THREADS>>>(samples, idx, bias, kern, out);
}

// round 9
// speedup vs baseline: 85.7304x; 85.7304x over previous
#include <cuda_runtime.h>
#include <cstdint>

// Problem constants (fixed by the reference)
#define NQ       64            // qubits
#define NS       4096          // samples per unique circuit
#define NU       256           // unique circuits
#define NB       1024          // batch size
#define PARTS    8             // blocks per circuit
#define NSB      (NS / PARTS)  // samples per block = 512
#define CHUNKS_B (NSB / 32)    // 16 chunks of 32 samples
#define THREADS  256
#define NWARPS   (THREADS / 32)
#define GRID     (NU * PARTS)  // 2048

// Per-(circuit,part) partial energy sums and completion counter.
__device__ float        g_part[GRID];
__device__ unsigned int g_count;   // zero-initialized; reset by last block

// One ballot-transpose step. Ballots act directly on the 0/1 int components.
// Lane owns qubits (lane) and (lane+32). Column bit order is a consistent
// permutation of sample order (irrelevant for XOR-popcount counting).
__device__ __forceinline__ void tstep(const uint4 v, const uint32_t b,
                                      const uint32_t p,
                                      uint32_t& colA, uint32_t& colB)
{
    const uint32_t W0 = __ballot_sync(0xffffffffu, v.x);
    const uint32_t W1 = __ballot_sync(0xffffffffu, v.y);
    const uint32_t W2 = __ballot_sync(0xffffffffu, v.z);
    const uint32_t W3 = __ballot_sync(0xffffffffu, v.w);
    const uint32_t Wl = (b & 1) ? W1 : W0;
    const uint32_t Wh = (b & 1) ? W3 : W2;
    const uint32_t Ws = (b & 2) ? Wh : Wl;
    const uint32_t t  = Ws >> p;
    colA = (colA << 2) | (t & 1u)        | ((t >> 15) & 2u);
    colB = (colB << 2) | ((t >> 8) & 1u) | ((t >> 23) & 2u);
}

// One block per (circuit, eighth). Software-pipelined:
//   [load+transpose G0] [prefetch G1a] SYNC [consume G0 || G1a in flight]
//   [transpose G1a, load+transpose G1b] SYNC [consume G1]
__global__ void __launch_bounds__(THREADS)
energy_kernel(const int* __restrict__ samples,
              const int* __restrict__ idx,
              const float* __restrict__ bias,
              const float* __restrict__ kern,
              float* __restrict__ out)
{
    __shared__ uint32_t col[CHUNKS_B][NQ];   // 4 KB
    __shared__ float red[NWARPS];
    __shared__ bool s_last;

    const int tid  = threadIdx.x;
    const int lane = tid & 31;
    const int w    = tid >> 5;
    const int bx   = blockIdx.x;
    const int c    = bx >> 3;        // circuit
    const int part = bx & 7;         // eighth

    const uint4* base =
        (const uint4*)(samples + (size_t)c * (size_t)(NS * NQ))
        + (size_t)part * NSB * (NQ / 4);

    const uint32_t b = lane & 3;
    const uint32_t p = lane >> 2;

    // Tile decode: tid -> upper-triangle tile of the 16x16 grid.
    // GUARDED: the subtract loop must only run for tid < 136 — for larger
    // tid the loop term (16 - I) goes negative and the loop runs ~65K
    // iterations (the R6/R8 5-ms regression).
    const bool doTile = (tid < 136);
    int I = 0, J = 0;
    if (doTile) {
        int t = tid;
        while (t >= 16 - I) { t -= 16 - I; I++; }
        J = I + t;
    }
    const int q0 = I << 2, r0 = J << 2;
    const int qb = tid - 192;            // bias qubit for tid >= 192

    int cnt[4][4];
    #pragma unroll
    for (int i = 0; i < 4; i++)
        #pragma unroll
        for (int j = 0; j < 4; j++)
            cnt[i][j] = 0;
    int n1 = 0;

    const uint4* PA = base + (size_t)w * 512;         // chunk w
    const uint4* PB = base + (size_t)(8 + w) * 512;   // chunk 8+w

    // ---------------- Group 0: load + transpose chunk w --------------------
    {
        uint32_t colA = 0u, colB = 0u;
        uint4 v[8];
        #pragma unroll
        for (int j = 0; j < 8; j++) v[j] = __ldcs(&PA[j * 32 + lane]);
        #pragma unroll
        for (int j = 0; j < 8; j++) tstep(v[j], b, p, colA, colB);
        #pragma unroll
        for (int j = 0; j < 8; j++) v[j] = __ldcs(&PA[(8 + j) * 32 + lane]);
        #pragma unroll
        for (int j = 0; j < 8; j++) tstep(v[j], b, p, colA, colB);
        col[w][lane]      = colA;
        col[w][lane + 32] = colB;
    }

    // Prefetch first half of chunk 8+w; stays in flight across the barrier
    // and through the group-0 consume below.
    uint4 u[8];
    #pragma unroll
    for (int j = 0; j < 8; j++) u[j] = __ldcs(&PB[j * 32 + lane]);

    __syncthreads();

    // ---------------- Consume group 0 (chunks 0..7) ------------------------
    if (doTile) {
        #pragma unroll
        for (int ch = 0; ch < 8; ch++) {
            const uint4 a4 = *(const uint4*)&col[ch][q0];
            const uint4 b4 = *(const uint4*)&col[ch][r0];
            const uint32_t a[4]  = {a4.x, a4.y, a4.z, a4.w};
            const uint32_t bb[4] = {b4.x, b4.y, b4.z, b4.w};
            #pragma unroll
            for (int i = 0; i < 4; i++)
                #pragma unroll
                for (int j = 0; j < 4; j++)
                    cnt[i][j] += __popc(a[i] ^ bb[j]);
        }
    }
    if (tid >= 192) {
        #pragma unroll
        for (int ch = 0; ch < 8; ch++) n1 += __popc(col[ch][qb]);
    }

    // ---------------- Group 1: transpose prefetched + load rest ------------
    {
        uint32_t colA = 0u, colB = 0u;
        #pragma unroll
        for (int j = 0; j < 8; j++) tstep(u[j], b, p, colA, colB);
        #pragma unroll
        for (int j = 0; j < 8; j++) u[j] = __ldcs(&PB[(8 + j) * 32 + lane]);
        #pragma unroll
        for (int j = 0; j < 8; j++) tstep(u[j], b, p, colA, colB);
        col[8 + w][lane]      = colA;
        col[8 + w][lane + 32] = colB;
    }
    __syncthreads();

    // ---------------- Consume group 1 (chunks 8..15) -----------------------
    if (doTile) {
        #pragma unroll
        for (int ch = 8; ch < 16; ch++) {
            const uint4 a4 = *(const uint4*)&col[ch][q0];
            const uint4 b4 = *(const uint4*)&col[ch][r0];
            const uint32_t a[4]  = {a4.x, a4.y, a4.z, a4.w};
            const uint32_t bb[4] = {b4.x, b4.y, b4.z, b4.w};
            #pragma unroll
            for (int i = 0; i < 4; i++)
                #pragma unroll
                for (int j = 0; j < 4; j++)
                    cnt[i][j] += __popc(a[i] ^ bb[j]);
        }
    }
    if (tid >= 192) {
        #pragma unroll
        for (int ch = 8; ch < 16; ch++) n1 += __popc(col[ch][qb]);
    }

    // ---------------- Fold K + bias ----------------------------------------
    float acc = 0.f;
    if (doTile) {
        #pragma unroll
        for (int i = 0; i < 4; i++) {
            #pragma unroll
            for (int j = 0; j < 4; j++) {
                const int q = q0 + i, r = r0 + j;
                float kv = kern[q * NQ + r];
                if (I != J) kv += kern[r * NQ + q];   // symmetry fold
                acc += kv * (float)(NSB - 2 * cnt[i][j]);
            }
        }
    }
    if (tid >= 192) acc += bias[qb] * (float)(NSB - 2 * n1);

    // ---------------- Reduction + fused gather ----------------------------
    #pragma unroll
    for (int o = 16; o > 0; o >>= 1)
        acc += __shfl_down_sync(0xffffffffu, acc, o);
    if (lane == 0) red[w] = acc;
    __syncthreads();

    if (tid == 0) {
        float s = 0.f;
        #pragma unroll
        for (int i = 0; i < NWARPS; i++) s += red[i];
        g_part[bx] = s;
        __threadfence();
        const unsigned int done = atomicAdd(&g_count, 1u);
        s_last = (done == GRID - 1);
    }
    __syncthreads();

    if (s_last) {
        __threadfence();
        for (int i = tid; i < NB; i += THREADS) {
            const int u2 = idx[i];
            const float* gp = &g_part[u2 * PARTS];
            float s = 0.f;
            #pragma unroll
            for (int q = 0; q < PARTS; q++) s += gp[q];
            out[i] = s * (1.0f / (float)NS);
        }
        if (tid == 0) g_count = 0u;   // reset for next graph replay
    }
}

extern "C" void kernel_launch(void* const* d_in, const int* in_sizes, int n_in,
                              void* d_out, int out_size)
{
    const int*   samples = (const int*)d_in[0];
    const int*   idx     = (const int*)d_in[1];
    const float* bias    = (const float*)d_in[2];
    const float* kern    = (const float*)d_in[3];
    float*       out     = (float*)d_out;

    energy_kernel<<<GRID, THREADS>>>(samples, idx, bias, kern, out);
}